// round 1
// baseline (speedup 1.0000x reference)
#include <cuda_runtime.h>
#include <stdint.h>

// Problem constants (fixed shapes per reference setup_inputs)
#define BT    512          // B*T rows of (N, C)
#define NTOK  197
#define CDIM  768
#define TFR   16
#define HALF  (CDIM / 2)
#define LN_EPS 1e-5f

#define ROW4  (NTOK * CDIM / 4)        // float4s per (b,t) slab = 37824
#define TOTAL4 ((size_t)BT * NTOK * CDIM / 4)  // 19,353,600

// Scratch for per-(b,t) gates. Allocation-free per harness rules.
__device__ float g_gate1[BT];
__device__ float g_gate2[BT];

// ---------------------------------------------------------------------------
// Kernel A: per-cls-row LayerNorm -> ReLU -> (C->2) linear -> tanh gates
// One block per (b,t). 256 threads, 3 channels each (768 = 3*256).
// ---------------------------------------------------------------------------
__global__ __launch_bounds__(256) void gate_kernel(
    const float* __restrict__ x,
    const float* __restrict__ ln_gamma,
    const float* __restrict__ ln_beta,
    const float* __restrict__ fc_w,
    const float* __restrict__ fc_b)
{
    const int row = blockIdx.x;                         // bt index
    const float* xr = x + (size_t)row * NTOK * CDIM;    // token n == 0
    const int tid = threadIdx.x;
    const int wid = tid >> 5;
    const int lid = tid & 31;

    __shared__ float sa[8];
    __shared__ float sb[8];

    float v[3];
    float s = 0.f, s2 = 0.f;
#pragma unroll
    for (int i = 0; i < 3; i++) {
        v[i] = xr[tid + i * 256];
        s  += v[i];
        s2 += v[i] * v[i];
    }

    // ---- block reduce (sum, sumsq) ----
#pragma unroll
    for (int o = 16; o; o >>= 1) {
        s  += __shfl_xor_sync(0xffffffffu, s,  o);
        s2 += __shfl_xor_sync(0xffffffffu, s2, o);
    }
    if (lid == 0) { sa[wid] = s; sb[wid] = s2; }
    __syncthreads();
    if (tid < 32) {
        s  = (lid < 8) ? sa[lid] : 0.f;
        s2 = (lid < 8) ? sb[lid] : 0.f;
#pragma unroll
        for (int o = 4; o; o >>= 1) {
            s  += __shfl_xor_sync(0xffffffffu, s,  o);
            s2 += __shfl_xor_sync(0xffffffffu, s2, o);
        }
        if (tid == 0) { sa[0] = s; sb[0] = s2; }
    }
    __syncthreads();

    const float mu   = sa[0] * (1.f / CDIM);
    const float var  = sb[0] * (1.f / CDIM) - mu * mu;
    const float rstd = rsqrtf(var + LN_EPS);

    // ---- normalize, relu, dot with fc_w rows ----
    float d0 = 0.f, d1 = 0.f;
#pragma unroll
    for (int i = 0; i < 3; i++) {
        const int c = tid + i * 256;
        float h = (v[i] - mu) * rstd * ln_gamma[c] + ln_beta[c];
        h = fmaxf(h, 0.f);
        d0 += h * fc_w[c];          // fc_w[0, c]
        d1 += h * fc_w[CDIM + c];   // fc_w[1, c]
    }

#pragma unroll
    for (int o = 16; o; o >>= 1) {
        d0 += __shfl_xor_sync(0xffffffffu, d0, o);
        d1 += __shfl_xor_sync(0xffffffffu, d1, o);
    }
    __syncthreads();   // all reads of sa/sb above are done before reuse
    if (lid == 0) { sa[wid] = d0; sb[wid] = d1; }
    __syncthreads();
    if (tid == 0) {
        float t0 = 0.f, t1 = 0.f;
#pragma unroll
        for (int w = 0; w < 8; w++) { t0 += sa[w]; t1 += sb[w]; }
        g_gate1[row] = tanhf(t0 + fc_b[0]);   // gate[..., 0]
        g_gate2[row] = tanhf(t1 + fc_b[1]);   // gate[..., 1]
    }
}

// ---------------------------------------------------------------------------
// Kernel B: full-tensor copy; cls rows (n==0) get the gated time-shift mix.
//   out channel c < HALF : g2 path, mixes with frame t-1
//   out channel c >= HALF: g1 path, mixes with frame t+1
// One float4 per thread; float4 never straddles a (row, channel-half) boundary
// since CDIM = 768 and HALF = 384 are both multiples of 4.
// ---------------------------------------------------------------------------
__global__ __launch_bounds__(256) void copy_kernel(
    const float4* __restrict__ xin,
    float4* __restrict__ out)
{
    const size_t i = (size_t)blockIdx.x * blockDim.x + threadIdx.x;
    if (i >= TOTAL4) return;

    float4 val = xin[i];

    const unsigned elem = (unsigned)(i * 4);
    const unsigned row  = elem / CDIM;       // token row index (bt*NTOK + n)
    const unsigned n    = row % NTOK;

    if (n == 0) {
        const unsigned bt = row / NTOK;
        const unsigned t  = bt % TFR;
        const unsigned c  = elem % CDIM;

        if (c < HALF) {
            // new_g2 = g2*(1 - gate2[t]) + (t>0 ? gate2[t-1]*g2[t-1] : 0)
            const float r = 1.f - g_gate2[bt];
            val.x *= r; val.y *= r; val.z *= r; val.w *= r;
            if (t > 0) {
                const float gp = g_gate2[bt - 1];
                const float4 p = xin[i - (size_t)ROW4];
                val.x += gp * p.x; val.y += gp * p.y;
                val.z += gp * p.z; val.w += gp * p.w;
            }
        } else {
            // new_g1 = g1*(1 - gate1[t]) + (t<T-1 ? gate1[t+1]*g1[t+1] : 0)
            const float r = 1.f - g_gate1[bt];
            val.x *= r; val.y *= r; val.z *= r; val.w *= r;
            if (t < TFR - 1) {
                const float gn = g_gate1[bt + 1];
                const float4 q = xin[i + (size_t)ROW4];
                val.x += gn * q.x; val.y += gn * q.y;
                val.z += gn * q.z; val.w += gn * q.w;
            }
        }
    }

    out[i] = val;
}

// ---------------------------------------------------------------------------
extern "C" void kernel_launch(void* const* d_in, const int* in_sizes, int n_in,
                              void* d_out, int out_size)
{
    const float* x        = (const float*)d_in[0];
    const float* ln_gamma = (const float*)d_in[1];
    const float* ln_beta  = (const float*)d_in[2];
    const float* fc_w     = (const float*)d_in[3];
    const float* fc_b     = (const float*)d_in[4];
    // d_in[5] = num_frames (known constant TFR=16 for this shape variant)

    gate_kernel<<<BT, 256>>>(x, ln_gamma, ln_beta, fc_w, fc_b);

    const int threads = 256;
    const int blocks  = (int)((TOTAL4 + threads - 1) / threads);
    copy_kernel<<<blocks, threads>>>((const float4*)x, (float4*)d_out);
}

// round 2
// speedup vs baseline: 1.0139x; 1.0139x over previous
#include <cuda_runtime.h>
#include <stdint.h>

// Problem constants (fixed shapes per reference setup_inputs)
#define BT    512          // B*T rows of (N, C)
#define NTOK  197
#define CDIM  768
#define TFR   16
#define HALF  (CDIM / 2)
#define LN_EPS 1e-5f

#define ROW4  (NTOK * CDIM / 4)                 // float4s per (b,t) slab = 37824
#define TOTAL4 ((size_t)BT * NTOK * CDIM / 4)   // 19,353,600

// Scratch for per-(b,t) gates. Allocation-free per harness rules.
__device__ float g_gate1[BT];
__device__ float g_gate2[BT];

// ---------------------------------------------------------------------------
// Kernel A: per-cls-row LayerNorm -> ReLU -> (C->2) linear -> tanh gates.
// WARP-PER-ROW: 512 warps total (64 blocks x 8 warps). Pure shfl reductions,
// no shared memory, no __syncthreads. Each lane owns 6 float4 = 24 channels.
// ---------------------------------------------------------------------------
__global__ __launch_bounds__(256) void gate_kernel(
    const float* __restrict__ x,
    const float* __restrict__ ln_gamma,
    const float* __restrict__ ln_beta,
    const float* __restrict__ fc_w,
    const float* __restrict__ fc_b)
{
    const int gwarp = (blockIdx.x * 256 + threadIdx.x) >> 5;   // 0..511 = bt
    if (gwarp >= BT) return;
    const int lid = threadIdx.x & 31;

    const float4* xr = (const float4*)(x + (size_t)gwarp * NTOK * CDIM);

    float4 v[6];
    float s = 0.f, s2 = 0.f;
#pragma unroll
    for (int k = 0; k < 6; k++) {
        v[k] = xr[lid + k * 32];
        s  += v[k].x + v[k].y + v[k].z + v[k].w;
        s2 += v[k].x * v[k].x + v[k].y * v[k].y
            + v[k].z * v[k].z + v[k].w * v[k].w;
    }

#pragma unroll
    for (int o = 16; o; o >>= 1) {
        s  += __shfl_xor_sync(0xffffffffu, s,  o);
        s2 += __shfl_xor_sync(0xffffffffu, s2, o);
    }

    const float mu   = s  * (1.f / CDIM);
    const float var  = s2 * (1.f / CDIM) - mu * mu;
    const float rstd = rsqrtf(var + LN_EPS);

    const float4* g4  = (const float4*)ln_gamma;
    const float4* b4  = (const float4*)ln_beta;
    const float4* w04 = (const float4*)fc_w;            // row 0
    const float4* w14 = (const float4*)(fc_w + CDIM);   // row 1

    float d0 = 0.f, d1 = 0.f;
#pragma unroll
    for (int k = 0; k < 6; k++) {
        const int f = lid + k * 32;
        const float4 g = g4[f], b = b4[f], w0 = w04[f], w1 = w14[f];
        float h;
        h = fmaxf((v[k].x - mu) * rstd * g.x + b.x, 0.f); d0 += h * w0.x; d1 += h * w1.x;
        h = fmaxf((v[k].y - mu) * rstd * g.y + b.y, 0.f); d0 += h * w0.y; d1 += h * w1.y;
        h = fmaxf((v[k].z - mu) * rstd * g.z + b.z, 0.f); d0 += h * w0.z; d1 += h * w1.z;
        h = fmaxf((v[k].w - mu) * rstd * g.w + b.w, 0.f); d0 += h * w0.w; d1 += h * w1.w;
    }

#pragma unroll
    for (int o = 16; o; o >>= 1) {
        d0 += __shfl_xor_sync(0xffffffffu, d0, o);
        d1 += __shfl_xor_sync(0xffffffffu, d1, o);
    }

    if (lid == 0) {
        g_gate1[gwarp] = tanhf(d0 + fc_b[0]);   // gate[..., 0]
        g_gate2[gwarp] = tanhf(d1 + fc_b[1]);   // gate[..., 1]
    }
}

// ---------------------------------------------------------------------------
// Kernel B: full-tensor streaming copy; cls rows (n==0) get the gated
// time-shift mix. Streaming cache hints (evict-first) keep the 620 MB
// stream from thrashing L2.
// ---------------------------------------------------------------------------
__global__ __launch_bounds__(256) void copy_kernel(
    const float4* __restrict__ xin,
    float4* __restrict__ out)
{
    const size_t i = (size_t)blockIdx.x * blockDim.x + threadIdx.x;
    if (i >= TOTAL4) return;

    float4 val = __ldcs(xin + i);

    const unsigned elem = (unsigned)(i * 4);
    const unsigned row  = elem / CDIM;       // token row index (bt*NTOK + n)
    const unsigned n    = row % NTOK;

    if (n == 0) {
        const unsigned bt = row / NTOK;
        const unsigned t  = bt % TFR;
        const unsigned c  = elem % CDIM;

        if (c < HALF) {
            // new_g2 = g2*(1 - gate2[t]) + (t>0 ? gate2[t-1]*g2[t-1] : 0)
            const float r = 1.f - g_gate2[bt];
            val.x *= r; val.y *= r; val.z *= r; val.w *= r;
            if (t > 0) {
                const float gp = g_gate2[bt - 1];
                const float4 p = xin[i - (size_t)ROW4];
                val.x += gp * p.x; val.y += gp * p.y;
                val.z += gp * p.z; val.w += gp * p.w;
            }
        } else {
            // new_g1 = g1*(1 - gate1[t]) + (t<T-1 ? gate1[t+1]*g1[t+1] : 0)
            const float r = 1.f - g_gate1[bt];
            val.x *= r; val.y *= r; val.z *= r; val.w *= r;
            if (t < TFR - 1) {
                const float gn = g_gate1[bt + 1];
                const float4 q = xin[i + (size_t)ROW4];
                val.x += gn * q.x; val.y += gn * q.y;
                val.z += gn * q.z; val.w += gn * q.w;
            }
        }
    }

    __stcs(out + i, val);
}

// ---------------------------------------------------------------------------
extern "C" void kernel_launch(void* const* d_in, const int* in_sizes, int n_in,
                              void* d_out, int out_size)
{
    const float* x        = (const float*)d_in[0];
    const float* ln_gamma = (const float*)d_in[1];
    const float* ln_beta  = (const float*)d_in[2];
    const float* fc_w     = (const float*)d_in[3];
    const float* fc_b     = (const float*)d_in[4];
    // d_in[5] = num_frames (constant TFR=16 for this shape variant)

    gate_kernel<<<(BT * 32 + 255) / 256, 256>>>(x, ln_gamma, ln_beta, fc_w, fc_b);

    const int threads = 256;
    const int blocks  = (int)((TOTAL4 + threads - 1) / threads);
    copy_kernel<<<blocks, threads>>>((const float4*)x, (float4*)d_out);
}

// round 3
// speedup vs baseline: 1.0507x; 1.0363x over previous
#include <cuda_runtime.h>
#include <stdint.h>

// Problem constants (fixed shapes per reference setup_inputs)
#define BT    512          // B*T rows of (N, C)
#define NTOK  197
#define CDIM  768
#define TFR   16
#define HALF  (CDIM / 2)
#define LN_EPS 1e-5f

#define ROW4    (NTOK * CDIM / 4)                 // float4s per (b,t) slab = 37824
#define TOTAL4  ((size_t)BT * NTOK * CDIM / 4)    // 19,353,600
#define F4_PER_BLOCK 1024                          // 256 threads x 4
#define NB_BULK ((int)(TOTAL4 / F4_PER_BLOCK))     // 18900 (exact)
#define CLS4    (CDIM / 4)                         // 192 float4s per cls row

// ---------------------------------------------------------------------------
// Warp-collective: LayerNorm -> ReLU -> (C->2) linear -> tanh gates for the
// cls row of one (b,t). Every lane returns the final (g1, g2).
// ---------------------------------------------------------------------------
__device__ __forceinline__ void warp_gates(
    const float* __restrict__ x, int bt,
    const float* __restrict__ ln_gamma,
    const float* __restrict__ ln_beta,
    const float* __restrict__ fc_w,
    const float* __restrict__ fc_b,
    int lid, float& g1, float& g2)
{
    const float4* xr = (const float4*)(x + (size_t)bt * NTOK * CDIM);

    float4 v[6];
    float s = 0.f, s2 = 0.f;
#pragma unroll
    for (int k = 0; k < 6; k++) {
        v[k] = xr[lid + k * 32];
        s  += v[k].x + v[k].y + v[k].z + v[k].w;
        s2 += v[k].x * v[k].x + v[k].y * v[k].y
            + v[k].z * v[k].z + v[k].w * v[k].w;
    }
#pragma unroll
    for (int o = 16; o; o >>= 1) {
        s  += __shfl_xor_sync(0xffffffffu, s,  o);
        s2 += __shfl_xor_sync(0xffffffffu, s2, o);
    }
    const float mu   = s  * (1.f / CDIM);
    const float var  = s2 * (1.f / CDIM) - mu * mu;
    const float rstd = rsqrtf(var + LN_EPS);

    const float4* g4  = (const float4*)ln_gamma;
    const float4* b4  = (const float4*)ln_beta;
    const float4* w04 = (const float4*)fc_w;            // row 0
    const float4* w14 = (const float4*)(fc_w + CDIM);   // row 1

    float d0 = 0.f, d1 = 0.f;
#pragma unroll
    for (int k = 0; k < 6; k++) {
        const int f = lid + k * 32;
        const float4 g = g4[f], b = b4[f], w0 = w04[f], w1 = w14[f];
        float h;
        h = fmaxf((v[k].x - mu) * rstd * g.x + b.x, 0.f); d0 += h * w0.x; d1 += h * w1.x;
        h = fmaxf((v[k].y - mu) * rstd * g.y + b.y, 0.f); d0 += h * w0.y; d1 += h * w1.y;
        h = fmaxf((v[k].z - mu) * rstd * g.z + b.z, 0.f); d0 += h * w0.z; d1 += h * w1.z;
        h = fmaxf((v[k].w - mu) * rstd * g.w + b.w, 0.f); d0 += h * w0.w; d1 += h * w1.w;
    }
#pragma unroll
    for (int o = 16; o; o >>= 1) {
        d0 += __shfl_xor_sync(0xffffffffu, d0, o);
        d1 += __shfl_xor_sync(0xffffffffu, d1, o);
    }
    g1 = tanhf(d0 + fc_b[0]);
    g2 = tanhf(d1 + fc_b[1]);
}

// ---------------------------------------------------------------------------
// Fused kernel.
//  Blocks [0, NB_BULK):   bulk copy, 1024 consecutive float4s per block,
//                         4 front-batched loads per thread; cls writes skipped.
//  Blocks [NB_BULK, +BT): one block per (b,t) cls row. Warps 0/1/2 compute
//                         gates for rows bt / bt-1 / bt+1, then threads
//                         0..191 write the mixed cls float4s.
// ---------------------------------------------------------------------------
__global__ __launch_bounds__(256) void fused_kernel(
    const float* __restrict__ xf,
    float* __restrict__ outf,
    const float* __restrict__ ln_gamma,
    const float* __restrict__ ln_beta,
    const float* __restrict__ fc_w,
    const float* __restrict__ fc_b)
{
    const float4* __restrict__ xin = (const float4*)xf;
    float4* __restrict__ out       = (float4*)outf;
    const int tid = threadIdx.x;

    if (blockIdx.x < NB_BULK) {
        // ---------------- bulk copy path ----------------
        const size_t base = (size_t)blockIdx.x * F4_PER_BLOCK + tid;

        float4 v[4];
#pragma unroll
        for (int k = 0; k < 4; k++)
            v[k] = __ldcs(xin + base + k * 256);

#pragma unroll
        for (int k = 0; k < 4; k++) {
            const size_t i = base + k * 256;
            const unsigned row = (unsigned)(i * 4) / CDIM;
            if (row % NTOK != 0)             // cls rows handled by cls blocks
                __stcs(out + i, v[k]);
        }
        return;
    }

    // ---------------- cls row path ----------------
    const int bt  = blockIdx.x - NB_BULK;    // 0..511
    const int t   = bt % TFR;
    const int wid = tid >> 5;
    const int lid = tid & 31;

    __shared__ float sg1_own, sg2_own, sg2_prev, sg1_next;

    if (wid == 0) {
        float g1, g2;
        warp_gates(xf, bt, ln_gamma, ln_beta, fc_w, fc_b, lid, g1, g2);
        if (lid == 0) { sg1_own = g1; sg2_own = g2; }
    } else if (wid == 1 && t > 0) {
        float g1, g2;
        warp_gates(xf, bt - 1, ln_gamma, ln_beta, fc_w, fc_b, lid, g1, g2);
        if (lid == 0) sg2_prev = g2;
    } else if (wid == 2 && t < TFR - 1) {
        float g1, g2;
        warp_gates(xf, bt + 1, ln_gamma, ln_beta, fc_w, fc_b, lid, g1, g2);
        if (lid == 0) sg1_next = g1;
    }
    __syncthreads();

    if (tid < CLS4) {
        const size_t i = (size_t)bt * ROW4 + tid;
        float4 val = xin[i];

        if (tid < HALF / 4) {
            // new_g2 = g2*(1 - gate2[bt]) + (t>0 ? gate2[bt-1]*g2[bt-1] : 0)
            const float r = 1.f - sg2_own;
            val.x *= r; val.y *= r; val.z *= r; val.w *= r;
            if (t > 0) {
                const float gp = sg2_prev;
                const float4 p = xin[i - (size_t)ROW4];
                val.x += gp * p.x; val.y += gp * p.y;
                val.z += gp * p.z; val.w += gp * p.w;
            }
        } else {
            // new_g1 = g1*(1 - gate1[bt]) + (t<T-1 ? gate1[bt+1]*g1[bt+1] : 0)
            const float r = 1.f - sg1_own;
            val.x *= r; val.y *= r; val.z *= r; val.w *= r;
            if (t < TFR - 1) {
                const float gn = sg1_next;
                const float4 q = xin[i + (size_t)ROW4];
                val.x += gn * q.x; val.y += gn * q.y;
                val.z += gn * q.z; val.w += gn * q.w;
            }
        }
        out[i] = val;
    }
}

// ---------------------------------------------------------------------------
extern "C" void kernel_launch(void* const* d_in, const int* in_sizes, int n_in,
                              void* d_out, int out_size)
{
    const float* x        = (const float*)d_in[0];
    const float* ln_gamma = (const float*)d_in[1];
    const float* ln_beta  = (const float*)d_in[2];
    const float* fc_w     = (const float*)d_in[3];
    const float* fc_b     = (const float*)d_in[4];
    // d_in[5] = num_frames (constant TFR=16 for this shape variant)

    fused_kernel<<<NB_BULK + BT, 256>>>(x, (float*)d_out,
                                        ln_gamma, ln_beta, fc_w, fc_b);
}

// round 4
// speedup vs baseline: 1.0528x; 1.0021x over previous
#include <cuda_runtime.h>
#include <stdint.h>

// Problem constants (fixed shapes per reference setup_inputs)
#define BT    512          // B*T rows of (N, C)
#define NTOK  197
#define CDIM  768
#define TFR   16
#define HALF  (CDIM / 2)
#define LN_EPS 1e-5f

#define ROW4    (NTOK * CDIM / 4)                 // float4s per (b,t) slab = 37824
#define TOTAL4  ((size_t)BT * NTOK * CDIM / 4)    // 19,353,600
#define F4_PER_BLOCK 1024                          // 256 threads x 4
#define NB_BULK ((int)(TOTAL4 / F4_PER_BLOCK))     // 18900 (exact)
#define CLS4    (CDIM / 4)                         // 192 float4s per cls row

// ---------------------------------------------------------------------------
// Warp-collective: LayerNorm -> ReLU -> (C->2) linear -> tanh gates for the
// cls row of one (b,t). Every lane returns the final (g1, g2).
// ---------------------------------------------------------------------------
__device__ __forceinline__ void warp_gates(
    const float* __restrict__ x, int bt,
    const float* __restrict__ ln_gamma,
    const float* __restrict__ ln_beta,
    const float* __restrict__ fc_w,
    const float* __restrict__ fc_b,
    int lid, float& g1, float& g2)
{
    const float4* xr = (const float4*)(x + (size_t)bt * NTOK * CDIM);

    float4 v[6];
    float s = 0.f, s2 = 0.f;
#pragma unroll
    for (int k = 0; k < 6; k++) {
        v[k] = xr[lid + k * 32];
        s  += v[k].x + v[k].y + v[k].z + v[k].w;
        s2 += v[k].x * v[k].x + v[k].y * v[k].y
            + v[k].z * v[k].z + v[k].w * v[k].w;
    }
#pragma unroll
    for (int o = 16; o; o >>= 1) {
        s  += __shfl_xor_sync(0xffffffffu, s,  o);
        s2 += __shfl_xor_sync(0xffffffffu, s2, o);
    }
    const float mu   = s  * (1.f / CDIM);
    const float var  = s2 * (1.f / CDIM) - mu * mu;
    const float rstd = rsqrtf(var + LN_EPS);

    const float4* g4  = (const float4*)ln_gamma;
    const float4* b4  = (const float4*)ln_beta;
    const float4* w04 = (const float4*)fc_w;            // row 0
    const float4* w14 = (const float4*)(fc_w + CDIM);   // row 1

    float d0 = 0.f, d1 = 0.f;
#pragma unroll
    for (int k = 0; k < 6; k++) {
        const int f = lid + k * 32;
        const float4 g = g4[f], b = b4[f], w0 = w04[f], w1 = w14[f];
        float h;
        h = fmaxf((v[k].x - mu) * rstd * g.x + b.x, 0.f); d0 += h * w0.x; d1 += h * w1.x;
        h = fmaxf((v[k].y - mu) * rstd * g.y + b.y, 0.f); d0 += h * w0.y; d1 += h * w1.y;
        h = fmaxf((v[k].z - mu) * rstd * g.z + b.z, 0.f); d0 += h * w0.z; d1 += h * w1.z;
        h = fmaxf((v[k].w - mu) * rstd * g.w + b.w, 0.f); d0 += h * w0.w; d1 += h * w1.w;
    }
#pragma unroll
    for (int o = 16; o; o >>= 1) {
        d0 += __shfl_xor_sync(0xffffffffu, d0, o);
        d1 += __shfl_xor_sync(0xffffffffu, d1, o);
    }
    g1 = tanhf(d0 + fc_b[0]);
    g2 = tanhf(d1 + fc_b[1]);
}

// ---------------------------------------------------------------------------
// Fused kernel.
//  Blocks [0, NB_BULK):   bulk copy, 1024 consecutive float4s per block,
//                         4 front-batched loads per thread; cls writes skipped.
//  Blocks [NB_BULK, +BT): one block per (b,t) cls row. Warps 0/1/2 compute
//                         gates for rows bt / bt-1 / bt+1, then threads
//                         0..191 write the mixed cls float4s.
// ---------------------------------------------------------------------------
__global__ __launch_bounds__(256) void fused_kernel(
    const float* __restrict__ xf,
    float* __restrict__ outf,
    const float* __restrict__ ln_gamma,
    const float* __restrict__ ln_beta,
    const float* __restrict__ fc_w,
    const float* __restrict__ fc_b)
{
    const float4* __restrict__ xin = (const float4*)xf;
    float4* __restrict__ out       = (float4*)outf;
    const int tid = threadIdx.x;

    if (blockIdx.x < NB_BULK) {
        // ---------------- bulk copy path ----------------
        const size_t base = (size_t)blockIdx.x * F4_PER_BLOCK + tid;

        float4 v[4];
#pragma unroll
        for (int k = 0; k < 4; k++)
            v[k] = __ldcs(xin + base + k * 256);

#pragma unroll
        for (int k = 0; k < 4; k++) {
            const size_t i = base + k * 256;
            const unsigned row = (unsigned)(i * 4) / CDIM;
            if (row % NTOK != 0)             // cls rows handled by cls blocks
                __stcs(out + i, v[k]);
        }
        return;
    }

    // ---------------- cls row path ----------------
    const int bt  = blockIdx.x - NB_BULK;    // 0..511
    const int t   = bt % TFR;
    const int wid = tid >> 5;
    const int lid = tid & 31;

    __shared__ float sg1_own, sg2_own, sg2_prev, sg1_next;

    if (wid == 0) {
        float g1, g2;
        warp_gates(xf, bt, ln_gamma, ln_beta, fc_w, fc_b, lid, g1, g2);
        if (lid == 0) { sg1_own = g1; sg2_own = g2; }
    } else if (wid == 1 && t > 0) {
        float g1, g2;
        warp_gates(xf, bt - 1, ln_gamma, ln_beta, fc_w, fc_b, lid, g1, g2);
        if (lid == 0) sg2_prev = g2;
    } else if (wid == 2 && t < TFR - 1) {
        float g1, g2;
        warp_gates(xf, bt + 1, ln_gamma, ln_beta, fc_w, fc_b, lid, g1, g2);
        if (lid == 0) sg1_next = g1;
    }
    __syncthreads();

    if (tid < CLS4) {
        const size_t i = (size_t)bt * ROW4 + tid;
        float4 val = xin[i];

        if (tid < HALF / 4) {
            // new_g2 = g2*(1 - gate2[bt]) + (t>0 ? gate2[bt-1]*g2[bt-1] : 0)
            const float r = 1.f - sg2_own;
            val.x *= r; val.y *= r; val.z *= r; val.w *= r;
            if (t > 0) {
                const float gp = sg2_prev;
                const float4 p = xin[i - (size_t)ROW4];
                val.x += gp * p.x; val.y += gp * p.y;
                val.z += gp * p.z; val.w += gp * p.w;
            }
        } else {
            // new_g1 = g1*(1 - gate1[bt]) + (t<T-1 ? gate1[bt+1]*g1[bt+1] : 0)
            const float r = 1.f - sg1_own;
            val.x *= r; val.y *= r; val.z *= r; val.w *= r;
            if (t < TFR - 1) {
                const float gn = sg1_next;
                const float4 q = xin[i + (size_t)ROW4];
                val.x += gn * q.x; val.y += gn * q.y;
                val.z += gn * q.z; val.w += gn * q.w;
            }
        }
        out[i] = val;
    }
}

// ---------------------------------------------------------------------------
extern "C" void kernel_launch(void* const* d_in, const int* in_sizes, int n_in,
                              void* d_out, int out_size)
{
    const float* x        = (const float*)d_in[0];
    const float* ln_gamma = (const float*)d_in[1];
    const float* ln_beta  = (const float*)d_in[2];
    const float* fc_w     = (const float*)d_in[3];
    const float* fc_b     = (const float*)d_in[4];
    // d_in[5] = num_frames (constant TFR=16 for this shape variant)

    fused_kernel<<<NB_BULK + BT, 256>>>(x, (float*)d_out,
                                        ln_gamma, ln_beta, fc_w, fc_b);
}